// round 4
// baseline (speedup 1.0000x reference)
#include <cuda_runtime.h>
#include <math.h>

#define BATCH 128
#define SEQ   1024
#define INP   7
#define HID   64
#define OUTD  500
#define MTOT  (BATCH*SEQ)   // 131072
#define FTM   128
#define FTN   128
#define HSP   20

typedef unsigned long long u64;

__device__ float g_hT[(size_t)HID * MTOT];   // h transposed: g_hT[k][b*SEQ+t]
__device__ volatile int g_prog[BATCH];       // lstm progress (steps done); zero-init

// ---- f32x2 packed helpers ----
__device__ __forceinline__ u64 pack2(float a, float b) {
    u64 r;
    asm("mov.b64 %0, {%1, %2};" : "=l"(r)
        : "r"(__float_as_uint(a)), "r"(__float_as_uint(b)));
    return r;
}
__device__ __forceinline__ u64 ffma2(u64 a, u64 b, u64 c) {
    u64 d;
    asm("fma.rn.f32x2 %0, %1, %2, %3;" : "=l"(d) : "l"(a), "l"(b), "l"(c));
    return d;
}
__device__ __forceinline__ u64 fadd2(u64 a, u64 b) {
    u64 d;
    asm("add.rn.f32x2 %0, %1, %2;" : "=l"(d) : "l"(a), "l"(b));
    return d;
}
__device__ __forceinline__ void unpack2(u64 v, float& lo, float& hi) {
    unsigned int l, h;
    asm("mov.b64 {%0, %1}, %2;" : "=r"(l), "=r"(h) : "l"(v));
    lo = __uint_as_float(l); hi = __uint_as_float(h);
}
__device__ __forceinline__ float tanhf_fast(float x) {
    float y;
    asm("tanh.approx.f32 %0, %1;" : "=f"(y) : "f"(x));
    return y;
}

// shared memory overlay: lstm role vs fc role
union __align__(16) SmemU {
    struct {
        float xs[SEQ * INP];                 // 28 KB
        float hbuf[2][HID];                  // 512 B (16B-aligned offsets)
        float hstage[2][HID][HSP];           // 10 KB
    } l;
    struct {
        float As[HID][FTM];                  // 32 KB
        float Bs[HID][FTN];                  // 32 KB
    } f;
};

// ---------------------------------------------------------------------------
// LSTM role: one CTA per batch element, 256 threads (as round 3) + progress
// flags every 16 steps so fc CTAs can consume g_hT windows concurrently.
// ---------------------------------------------------------------------------
__device__ __forceinline__ void lstm_role(
    SmemU& sm, int b,
    const float* __restrict__ x,
    const float* __restrict__ W_ih,
    const float* __restrict__ W_hh,
    const float* __restrict__ b_ih,
    const float* __restrict__ b_hh)
{
    float* xs = sm.l.xs;
    const int tid  = threadIdx.x;
    const int hh   = tid >> 2;
    const int gate = tid & 3;
    const int row  = gate * HID + hh;
    const int lane = tid & 31;
    const int lb   = lane & ~3;

    // stage x[b]
    {
        const float4* src = (const float4*)(x + (size_t)b * SEQ * INP);
        float4* dst = (float4*)xs;
        #pragma unroll
        for (int i = 0; i < (SEQ*INP)/(4*256); ++i)
            dst[tid + i*256] = src[tid + i*256];
    }

    // W_hh row -> packed registers
    u64 w2[HID/2];
    {
        const ulonglong2* wr = (const ulonglong2*)(W_hh + (size_t)row * HID);
        #pragma unroll
        for (int i = 0; i < HID/4; ++i) {
            ulonglong2 v = wr[i];
            w2[2*i+0] = v.x; w2[2*i+1] = v.y;
        }
    }
    float wih[INP];
    #pragma unroll
    for (int i = 0; i < INP; ++i) wih[i] = W_ih[row*INP + i];
    const float bias = b_ih[row] + b_hh[row];

    const float sc  = (gate == 2) ? 1.0f : 0.5f;
    const float off = (gate == 2) ? 0.0f : 0.5f;

    if (tid < HID) sm.l.hbuf[0][tid] = 0.0f;
    float c = 0.0f;
    __syncthreads();

    float xacc = bias;
    #pragma unroll
    for (int i = 0; i < INP; ++i) xacc = fmaf(xs[i], wih[i], xacc);

    int cur = 0;
    for (int t = 0; t < SEQ; ++t) {
        const ulonglong2* hv = (const ulonglong2*)sm.l.hbuf[cur];
        u64 a[8];
        #pragma unroll
        for (int i = 0; i < 8; ++i) a[i] = 0ull;
        #pragma unroll
        for (int j = 0; j < 4; ++j) {
            ulonglong2 h0 = hv[4*j+0];
            ulonglong2 h1 = hv[4*j+1];
            ulonglong2 h2 = hv[4*j+2];
            ulonglong2 h3 = hv[4*j+3];
            a[0] = ffma2(h0.x, w2[8*j+0], a[0]);
            a[1] = ffma2(h0.y, w2[8*j+1], a[1]);
            a[2] = ffma2(h1.x, w2[8*j+2], a[2]);
            a[3] = ffma2(h1.y, w2[8*j+3], a[3]);
            a[4] = ffma2(h2.x, w2[8*j+4], a[4]);
            a[5] = ffma2(h2.y, w2[8*j+5], a[5]);
            a[6] = ffma2(h3.x, w2[8*j+6], a[6]);
            a[7] = ffma2(h3.y, w2[8*j+7], a[7]);
        }
        u64 s0 = fadd2(a[0], a[1]);
        u64 s1 = fadd2(a[2], a[3]);
        u64 s2 = fadd2(a[4], a[5]);
        u64 s3 = fadd2(a[6], a[7]);
        u64 s  = fadd2(fadd2(s0, s1), fadd2(s2, s3));
        float slo, shi; unpack2(s, slo, shi);
        float pre = xacc + slo + shi;

        float act = fmaf(sc, tanhf_fast(sc * pre), off);

        float ig = __shfl_sync(0xffffffffu, act, lb+0);
        float fg = __shfl_sync(0xffffffffu, act, lb+1);
        float gg = __shfl_sync(0xffffffffu, act, lb+2);
        float og = __shfl_sync(0xffffffffu, act, lb+3);

        c = fmaf(fg, c, ig*gg);
        float h = og * tanhf_fast(c);
        if (gate == 0) {
            sm.l.hbuf[cur ^ 1][hh] = h;
            sm.l.hstage[(t >> 4) & 1][hh][t & 15] = h;
        }

        // next-step x contribution (off critical path)
        int tn = (t + 1 < SEQ) ? t + 1 : 0;
        const float* xt = xs + tn*INP;
        float xn = bias;
        #pragma unroll
        for (int i = 0; i < INP; ++i) xn = fmaf(xt[i], wih[i], xn);
        xacc = xn;

        __syncthreads();
        cur ^= 1;

        if ((t & 15) == 15) {
            // coalesced dump of completed 16-step window
            int wsel = (t >> 4) & 1;
            int k = tid >> 2;
            int j = (tid & 3) * 4;
            const float* hp = &sm.l.hstage[wsel][k][j];
            float4 v = make_float4(hp[0], hp[1], hp[2], hp[3]);
            *(float4*)(g_hT + (size_t)k*MTOT + (size_t)b*SEQ + (t - 15) + j) = v;
            __threadfence();   // make dump visible before the next flag publish
        } else if ((t & 15) == 0 && t != 0) {
            // previous window's dump + fences are ordered before this point
            // by the barrier above (canonical producer pattern)
            if (tid == 0) g_prog[b] = t;
        }
    }
    __syncthreads();
    if (tid == 0) g_prog[b] = SEQ;
}

// ---------------------------------------------------------------------------
// FC role: one CTA per batch element (b = bid-128). For each 128-step window
// (after lstm publishes it): tile 128t x 128n, 256 threads, thread 16m x 4n,
// FFMA2 accumulators. A broadcast per warp (same m-strip), B coalesced.
// ---------------------------------------------------------------------------
__device__ __forceinline__ void fc_role(
    SmemU& sm, int b,
    const float* __restrict__ W_fc,
    const float* __restrict__ b_fc,
    float* __restrict__ out)
{
    const int tid = threadIdx.x;
    const int tx  = tid & 31;
    const int ty  = tid >> 5;
    const int n0  = tx * 4;
    const int m0  = ty * 16;

    for (int w = 0; w < 8; ++w) {
        if (tid == 0) {
            while (g_prog[b] < (w + 1) * 128) { }   // volatile spin
            __threadfence();                        // acquire
        }
        const int rowbase = b * SEQ + w * FTM;

        for (int nt = 0; nt < 4; ++nt) {
            __syncthreads();   // prior compute done; safe to overwrite tiles
            if (nt == 0) {
                // As[k][m] = g_hT[k][rowbase+m]  (coalesced, conflict-free)
                #pragma unroll
                for (int l2 = 0; l2 < 8; ++l2) {
                    int fid = tid + l2*256;
                    int k   = fid >> 5;
                    int m4  = (fid & 31) * 4;
                    *(float4*)&sm.f.As[k][m4] =
                        *(const float4*)(g_hT + (size_t)k*MTOT + rowbase + m4);
                }
            }
            const int col0 = nt * FTN;
            {   // Bs[k][n] = W_fc[col0+n][k] (pairs of threads per row)
                int n   = tid >> 1;
                int kf0 = (tid & 1) * 8;
                int r   = col0 + n;
                #pragma unroll
                for (int q = 0; q < 8; ++q) {
                    float4 v = make_float4(0.f,0.f,0.f,0.f);
                    if (r < OUTD)
                        v = *(const float4*)(W_fc + (size_t)r*HID + (kf0+q)*4);
                    int kk = (kf0+q)*4;
                    sm.f.Bs[kk+0][n] = v.x;
                    sm.f.Bs[kk+1][n] = v.y;
                    sm.f.Bs[kk+2][n] = v.z;
                    sm.f.Bs[kk+3][n] = v.w;
                }
            }
            __syncthreads();

            u64 acc[8][4];
            #pragma unroll
            for (int mm = 0; mm < 8; ++mm)
                #pragma unroll
                for (int nn = 0; nn < 4; ++nn) acc[mm][nn] = 0ull;

            const float* asr = &sm.f.As[0][m0];
            const float* bsr = &sm.f.Bs[0][n0];
            #pragma unroll 4
            for (int k = 0; k < HID; ++k) {
                ulonglong2 u0 = *(const ulonglong2*)(asr + 0);
                ulonglong2 u1 = *(const ulonglong2*)(asr + 4);
                ulonglong2 u2 = *(const ulonglong2*)(asr + 8);
                ulonglong2 u3 = *(const ulonglong2*)(asr + 12);
                float4 bv = *(const float4*)(bsr);
                asr += FTM; bsr += FTN;
                u64 b2[4];
                b2[0] = pack2(bv.x, bv.x);
                b2[1] = pack2(bv.y, bv.y);
                b2[2] = pack2(bv.z, bv.z);
                b2[3] = pack2(bv.w, bv.w);
                u64 ap[8] = {u0.x,u0.y,u1.x,u1.y,u2.x,u2.y,u3.x,u3.y};
                #pragma unroll
                for (int nn = 0; nn < 4; ++nn) {
                    #pragma unroll
                    for (int mm = 0; mm < 8; ++mm)
                        acc[mm][nn] = ffma2(ap[mm], b2[nn], acc[mm][nn]);
                }
            }

            if (col0 + n0 < OUTD) {   // 500%4==0: 4-strip all-in/all-out
                float4 bias = *(const float4*)(b_fc + col0 + n0);
                const float bb[4] = {bias.x, bias.y, bias.z, bias.w};
                #pragma unroll
                for (int mm = 0; mm < 8; ++mm) {
                    float lo[4], hi[4];
                    #pragma unroll
                    for (int nn = 0; nn < 4; ++nn) unpack2(acc[mm][nn], lo[nn], hi[nn]);
                    int r0 = rowbase + m0 + 2*mm;
                    float4 o0, o1;
                    o0.x=lo[0]+bb[0]; o0.y=lo[1]+bb[1]; o0.z=lo[2]+bb[2]; o0.w=lo[3]+bb[3];
                    o1.x=hi[0]+bb[0]; o1.y=hi[1]+bb[1]; o1.z=hi[2]+bb[2]; o1.w=hi[3]+bb[3];
                    *(float4*)(out + (size_t)r0     * OUTD + col0 + n0) = o0;
                    *(float4*)(out + (size_t)(r0+1) * OUTD + col0 + n0) = o1;
                }
            }
        }
    }
}

// ---------------------------------------------------------------------------
// Fused kernel: blocks 0..127 run the recurrence, blocks 128..255 run the FC
// consumer for batch bid-128. Classic placement maps bid and bid+148 to the
// same SM -> (lstm, fc) pairs co-reside; 128-reg cap + 64KB smem union give
// 2 CTAs/SM. If co-residency fails, execution degrades to serialized (safe).
// ---------------------------------------------------------------------------
__global__ __launch_bounds__(256, 2)
void fused_kernel(const float* __restrict__ x,
                  const float* __restrict__ W_ih,
                  const float* __restrict__ W_hh,
                  const float* __restrict__ b_ih,
                  const float* __restrict__ b_hh,
                  const float* __restrict__ W_fc,
                  const float* __restrict__ b_fc,
                  float* __restrict__ out)
{
    __shared__ SmemU sm;
    const int bx = blockIdx.x;
    if (bx < BATCH) {
        lstm_role(sm, bx, x, W_ih, W_hh, b_ih, b_hh);
    } else {
        fc_role(sm, bx - BATCH, W_fc, b_fc, out);
    }
}

extern "C" void kernel_launch(void* const* d_in, const int* in_sizes, int n_in,
                              void* d_out, int out_size)
{
    const float* x    = (const float*)d_in[0];
    const float* W_ih = (const float*)d_in[1];
    const float* W_hh = (const float*)d_in[2];
    const float* b_ih = (const float*)d_in[3];
    const float* b_hh = (const float*)d_in[4];
    const float* W_fc = (const float*)d_in[5];
    const float* b_fc = (const float*)d_in[6];
    float* out = (float*)d_out;

    fused_kernel<<<2*BATCH, 256>>>(x, W_ih, W_hh, b_ih, b_hh, W_fc, b_fc, out);
}